// round 15
// baseline (speedup 1.0000x reference)
#include <cuda_runtime.h>
#include <cstdint>

#define BSZ 32
#define CCH 256
#define NPX 4096
#define REGF 0.01f

#define TN  16                      // n per block
#define KB  4                       // b per chunk
#define NCHUNK (BSZ / KB)           // 8
#define RST 68                      // row stride in floats (64 data + 4 pad)
#define BUFSZ (64 * RST)            // 4352 floats per buffer
#define NBUF 4                      // 4 buffers = 69,632 B per CTA

typedef unsigned long long ull;

// packed fp32x2 FMA (2 FMAs/instr); ptxas never emits from C++.
__device__ __forceinline__ void ffma2(ull& acc, ull a, ull b) {
    asm("fma.rn.f32x2 %0, %1, %2, %0;" : "+l"(acc) : "l"(a), "l"(b));
}
__device__ __forceinline__ unsigned smem_u32(const void* p) {
    return (unsigned)__cvta_generic_to_shared(p);
}
__device__ __forceinline__ void cp16(unsigned s, const float* g) {
    asm volatile("cp.async.cg.shared.global [%0], [%1], 16;" :: "r"(s), "l"(g));
}
#define CP_COMMIT() asm volatile("cp.async.commit_group;" ::: "memory")
#define CP_WAIT2()  asm volatile("cp.async.wait_group 2;" ::: "memory")

// ---------------------------------------------------------------------------
// Kernel 1: mean over batch. x: [B, C, N], mean: [C, N].
// ---------------------------------------------------------------------------
__global__ void mvg_mean_kernel(const float* __restrict__ x,
                                float* __restrict__ mean) {
    int idx = blockIdx.x * blockDim.x + threadIdx.x;
    const float4* x4 = (const float4*)x;
    float4 s = make_float4(0.f, 0.f, 0.f, 0.f);
    const int stride = CCH * NPX / 4;
#pragma unroll
    for (int b = 0; b < BSZ; b++) {
        float4 v = x4[b * stride + idx];
        s.x += v.x; s.y += v.y; s.z += v.z; s.w += v.w;
    }
    const float inv = 1.0f / BSZ;
    s.x *= inv; s.y *= inv; s.z *= inv; s.w *= inv;
    ((float4*)mean)[idx] = s;
}

// ---------------------------------------------------------------------------
// Kernel 2: cov[c,d,n] = (sum_b x_c x_d - B m_c m_d)/(B-1) + REG*(c==d)
// Block = 32c x 32d x 16n, 256 threads, microtile 8c x 4d x 2n (64 acc regs
// -> <=128 regs -> TWO CTAs/SM = 16 warps, real occupancy doubling).
// Thread map: tn = tid[0:3) (n-pair), td = tid[3:6) (8 pos x 4 d-rows),
// tc = tid[6:8) (4 pos x 8 c-rows). av rows are warp-uniform (broadcast
// LDS); bv row-groups at stride 4*RST = 272 ≡ 16 (mod 32 banks) ->
// conflict-free phases. smem rows padded to RST=68 floats.
// Upper-tri tile pairs (36), mirrored writes. cp.async 4 buffers,
// 3 chunks in flight, one sync per chunk.
// ---------------------------------------------------------------------------
__global__ __launch_bounds__(256, 2)
void mvg_cov_kernel(const float* __restrict__ x,
                    const float* __restrict__ mean,
                    float* __restrict__ cov) {
    // upper-triangular tile pair (ti <= tj) from blockIdx.x in [0,36)
    int rem = blockIdx.x;
    int ti = 0, row8 = 8;
    while (rem >= row8) { rem -= row8; row8--; ti++; }
    const int tj = ti + rem;
    const bool diag = (ti == tj);
    const int n0 = blockIdx.y * TN;

    extern __shared__ float sm[];

    const int tid = threadIdx.x;
    const int tn  = tid & 7;         // n-pair (2 n per thread)
    const int td  = (tid >> 3) & 7;  // 8 d-positions (4 rows each)
    const int tc  = tid >> 6;        // 4 c-positions (8 rows each)

    // r-invariant staging fields
    const int n4 = tid & 3;          // float4 column (0..3)
    const int sb = (tid >> 2) & 3;   // batch-within-chunk
    const int r0 = tid >> 4;         // base row (0..15); rows r0, r0+16

    const float* gc_base = x + ((size_t)sb * CCH + ti * 32 + r0) * NPX + n0 + n4 * 4;
    const float* gd_base = x + ((size_t)sb * CCH + tj * 32 + r0) * NPX + n0 + n4 * 4;
    const unsigned sm_off = (unsigned)((r0 * RST + sb * 16 + n4 * 4) * 4);

    // ---- stage chunk ck into buffer ck % NBUF ----
    auto stage = [&](int ck) {
        const unsigned dst = smem_u32(sm)
            + (unsigned)((ck & (NBUF - 1)) * BUFSZ * 4) + sm_off;
        const size_t gofs = (size_t)(ck * KB) * CCH * NPX;
        const float* gc = gc_base + gofs;
        cp16(dst, gc);
        cp16(dst + (unsigned)(16 * RST * 4), gc + (size_t)16 * NPX);
        if (!diag) {
            const float* gd = gd_base + gofs;
            const unsigned dd = dst + (unsigned)(32 * RST * 4);
            cp16(dd, gd);
            cp16(dd + (unsigned)(16 * RST * 4), gd + (size_t)16 * NPX);
        }
        CP_COMMIT();
    };

    ull acc[8][4];
#pragma unroll
    for (int i = 0; i < 8; i++)
#pragma unroll
        for (int j = 0; j < 4; j++) acc[i][j] = 0ull;

    const int drow0 = diag ? 0 : 32;

    auto compute = [&](int ck) {
        const float* buf = sm + (ck & (NBUF - 1)) * BUFSZ;
        const float* pa = buf + (tc * 8) * RST + 2 * tn;
        const float* pb = buf + (drow0 + td * 4) * RST + 2 * tn;
#pragma unroll
        for (int bb = 0; bb < KB; bb++) {
            ull av[8], bv[4];
#pragma unroll
            for (int i = 0; i < 8; i++)
                av[i] = *(const ull*)&pa[i * RST + bb * 16];
#pragma unroll
            for (int j = 0; j < 4; j++)
                bv[j] = *(const ull*)&pb[j * RST + bb * 16];
#pragma unroll
            for (int i = 0; i < 8; i++)
#pragma unroll
                for (int j = 0; j < 4; j++)
                    ffma2(acc[i][j], av[i], bv[j]);
        }
    };

    // ---- pipeline: 4 buffers, 3 chunks in flight, one sync per chunk ----
    stage(0); stage(1); stage(2);
#pragma unroll
    for (int ck = 0; ck < NCHUNK; ck++) {
        CP_WAIT2();                  // groups 0..ck complete
        __syncthreads();             // data visible; prev compute done
        compute(ck);
        if (ck + 3 < NCHUNK) stage(ck + 3);
        else CP_COMMIT();            // empty group keeps wait count aligned
    }

    // ---- epilogue: mean correction, scale, reg, write + mirror ----
    const float scale = 1.0f / (BSZ - 1);
    const int n = n0 + 2 * tn;
    float2 md[4];
#pragma unroll
    for (int j = 0; j < 4; j++)
        md[j] = *(const float2*)&mean[(size_t)(tj * 32 + td * 4 + j) * NPX + n];
#pragma unroll
    for (int i = 0; i < 8; i++) {
        const int c = ti * 32 + tc * 8 + i;
        float2 mc = *(const float2*)&mean[(size_t)c * NPX + n];
#pragma unroll
        for (int j = 0; j < 4; j++) {
            const int d = tj * 32 + td * 4 + j;
            ull a = acc[i][j];
            float lo = __uint_as_float((unsigned)(a & 0xffffffffull));
            float hi = __uint_as_float((unsigned)(a >> 32));
            lo = (lo - (float)BSZ * mc.x * md[j].x) * scale;
            hi = (hi - (float)BSZ * mc.y * md[j].y) * scale;
            if (c == d) { lo += REGF; hi += REGF; }
            float2 o = make_float2(lo, hi);
            __stcs((float2*)&cov[((size_t)c * CCH + d) * NPX + n], o);
            if (!diag)
                __stcs((float2*)&cov[((size_t)d * CCH + c) * NPX + n], o);
        }
    }
}

// ---------------------------------------------------------------------------
extern "C" void kernel_launch(void* const* d_in, const int* in_sizes, int n_in,
                              void* d_out, int out_size) {
    const float* x = (const float*)d_in[0];
    float* out  = (float*)d_out;
    float* mean = out;                          // [C, N]
    float* cov  = out + (size_t)CCH * NPX;      // [C, C, N]

    mvg_mean_kernel<<<(CCH * NPX / 4) / 256, 256>>>(x, mean);

    static bool attr_set = false;
    const int smem_bytes = NBUF * BUFSZ * 4;    // 69,632 B per CTA
    if (!attr_set) {
        cudaFuncSetAttribute(mvg_cov_kernel,
                             cudaFuncAttributeMaxDynamicSharedMemorySize,
                             smem_bytes);
        attr_set = true;
    }
    dim3 grid(36, NPX / TN);                    // (36, 256)
    mvg_cov_kernel<<<grid, 256, smem_bytes>>>(x, mean, cov);
}

// round 16
// speedup vs baseline: 1.0683x; 1.0683x over previous
#include <cuda_runtime.h>
#include <cstdint>

#define BSZ 32
#define CCH 256
#define NPX 4096
#define REGF 0.01f

#define TN  32                      // n per block
#define KB  4                       // b per chunk
#define NCHUNK (BSZ / KB)           // 8
#define BUFSZ (64 * KB * TN)        // 8192 floats (32 KB): 64 rows x 4 b x 32 n
#define NBUF 4                      // 128 KB total

typedef unsigned long long ull;

// packed fp32x2 FMA (2 FMAs/instr); ptxas never emits from C++.
__device__ __forceinline__ void ffma2(ull& acc, ull a, ull b) {
    asm("fma.rn.f32x2 %0, %1, %2, %0;" : "+l"(acc) : "l"(a), "l"(b));
}
__device__ __forceinline__ unsigned smem_u32(const void* p) {
    return (unsigned)__cvta_generic_to_shared(p);
}
__device__ __forceinline__ void cp16(unsigned s, const float* g) {
    asm volatile("cp.async.cg.shared.global [%0], [%1], 16;" :: "r"(s), "l"(g));
}
#define CP_COMMIT() asm volatile("cp.async.commit_group;" ::: "memory")
#define CP_WAIT2()  asm volatile("cp.async.wait_group 2;" ::: "memory")

#define ONE2 0x3f8000003f800000ull   // packed {1.0f, 1.0f}

// ---------------------------------------------------------------------------
// Fused kernel: mean AND covariance in one pass.
//   cov[c,d,n] = (sum_b x_c x_d - (sum_b x_c)(sum_b x_d)/B)/(B-1) + REG*(c==d)
//   mean[c,n]  = (sum_b x_c)/B            (written by diagonal blocks)
// Block = 32c x 32d tile pair (36 upper-tri pairs, mirrored writes) x 32 n.
// Thread microtile 8c x 8d x 2n packed f32x2. Row sums asum/bsum are
// accumulated with ffma2(.,.,ONE2) on the already-loaded av/bv values:
// zero extra LDS, and the separate mean kernel (a full 128MB read pass)
// plus all epilogue mean loads are eliminated.
// Pipeline: cp.async, 4 buffers, KB=4 chunks, 3 in flight, one sync/chunk.
// ---------------------------------------------------------------------------
__global__ __launch_bounds__(256, 1)
void mvg_fused_kernel(const float* __restrict__ x,
                      float* __restrict__ mean,
                      float* __restrict__ cov) {
    // upper-triangular tile pair (ti <= tj) from blockIdx.x in [0,36)
    int rem = blockIdx.x;
    int ti = 0, row8 = 8;
    while (rem >= row8) { rem -= row8; row8--; ti++; }
    const int tj = ti + rem;
    const bool diag = (ti == tj);
    const int n0 = blockIdx.y * TN;

    extern __shared__ float sm[];

    const int tid = threadIdx.x;
    const int tn  = tid & 15;        // n-pair index (2 n per thread)
    const int tcd = tid >> 4;
    const int tc  = tcd & 3;         // 8 c-rows
    const int td  = tcd >> 2;        // 8 d-rows

    // r-invariant staging fields: f = r*256 + tid
    const int n4 = tid & 7;          // float4 column (0..7)
    const int sb = (tid >> 3) & 3;   // batch-within-chunk
    const int r0 = tid >> 5;         // base row (0..7); row = r0 + 8r

    const float* gc_base = x + ((size_t)sb * CCH + ti * 32 + r0) * NPX + n0 + n4 * 4;
    const float* gd_base = x + ((size_t)sb * CCH + tj * 32 + r0) * NPX + n0 + n4 * 4;
    const unsigned sm_off = (unsigned)(((r0 * KB + sb) * TN + n4 * 4) * 4);

    // ---- stage chunk ck into buffer ck % NBUF (fully unrolled) ----
    auto stage = [&](int ck) {
        const unsigned dst = smem_u32(sm)
            + (unsigned)((ck & (NBUF - 1)) * BUFSZ * 4) + sm_off;
        const size_t gofs = (size_t)(ck * KB) * CCH * NPX;
        const float* gc = gc_base + gofs;
#pragma unroll
        for (int r = 0; r < 4; r++)   // c-rows r0 + 8r (0..31)
            cp16(dst + (unsigned)(r * 8 * KB * TN * 4), gc + (size_t)r * 8 * NPX);
        if (!diag) {
            const float* gd = gd_base + gofs;
            const unsigned ddst = dst + (unsigned)(32 * KB * TN * 4);
#pragma unroll
            for (int r = 0; r < 4; r++)  // d-rows
                cp16(ddst + (unsigned)(r * 8 * KB * TN * 4), gd + (size_t)r * 8 * NPX);
        }
        CP_COMMIT();
    };

    ull acc[8][8];
    ull asum[8], bsum[8];
#pragma unroll
    for (int i = 0; i < 8; i++) {
        asum[i] = 0ull; bsum[i] = 0ull;
#pragma unroll
        for (int j = 0; j < 8; j++) acc[i][j] = 0ull;
    }

    const int drow0 = diag ? 0 : 32;

    auto compute = [&](int ck) {
        const float* buf = sm + (ck & (NBUF - 1)) * BUFSZ;
        const float* pa = buf + (tc * 8) * (KB * TN) + 2 * tn;
        const float* pb = buf + (drow0 + td * 8) * (KB * TN) + 2 * tn;
#pragma unroll
        for (int bb = 0; bb < KB; bb++) {
            ull av[8], bv[8];
#pragma unroll
            for (int i = 0; i < 8; i++)
                av[i] = *(const ull*)&pa[i * (KB * TN) + bb * TN];
#pragma unroll
            for (int j = 0; j < 8; j++)
                bv[j] = *(const ull*)&pb[j * (KB * TN) + bb * TN];
#pragma unroll
            for (int i = 0; i < 8; i++) ffma2(asum[i], av[i], ONE2);
#pragma unroll
            for (int j = 0; j < 8; j++) ffma2(bsum[j], bv[j], ONE2);
#pragma unroll
            for (int i = 0; i < 8; i++)
#pragma unroll
                for (int j = 0; j < 8; j++)
                    ffma2(acc[i][j], av[i], bv[j]);
        }
    };

    // ---- pipeline: 4 buffers, 3 chunks in flight, one sync per chunk ----
    stage(0); stage(1); stage(2);
#pragma unroll
    for (int ck = 0; ck < NCHUNK; ck++) {
        CP_WAIT2();                  // groups 0..ck complete
        __syncthreads();             // data visible; prev compute done
        compute(ck);
        if (ck + 3 < NCHUNK) stage(ck + 3);
        else CP_COMMIT();            // empty group keeps wait count aligned
    }

    // ---- epilogue ----
    const float scale = 1.0f / (BSZ - 1);
    const float invB  = 1.0f / BSZ;
    const int n = n0 + 2 * tn;

    float2 ma[8], mb[8];             // raw sums, unpacked
#pragma unroll
    for (int i = 0; i < 8; i++) {
        ma[i] = make_float2(__uint_as_float((unsigned)(asum[i] & 0xffffffffull)),
                            __uint_as_float((unsigned)(asum[i] >> 32)));
        mb[i] = make_float2(__uint_as_float((unsigned)(bsum[i] & 0xffffffffull)),
                            __uint_as_float((unsigned)(bsum[i] >> 32)));
    }

    // mean: written once per (c,n) by diagonal blocks, td==0 threads
    if (diag && td == 0) {
#pragma unroll
        for (int i = 0; i < 8; i++) {
            const int c = ti * 32 + tc * 8 + i;
            __stcs((float2*)&mean[(size_t)c * NPX + n],
                   make_float2(ma[i].x * invB, ma[i].y * invB));
        }
    }

#pragma unroll
    for (int i = 0; i < 8; i++) {
        const int c = ti * 32 + tc * 8 + i;
#pragma unroll
        for (int j = 0; j < 8; j++) {
            const int d = tj * 32 + td * 8 + j;
            ull a = acc[i][j];
            float lo = __uint_as_float((unsigned)(a & 0xffffffffull));
            float hi = __uint_as_float((unsigned)(a >> 32));
            lo = (lo - ma[i].x * mb[j].x * invB) * scale;
            hi = (hi - ma[i].y * mb[j].y * invB) * scale;
            if (c == d) { lo += REGF; hi += REGF; }
            float2 o = make_float2(lo, hi);
            __stcs((float2*)&cov[((size_t)c * CCH + d) * NPX + n], o);
            if (!diag)
                __stcs((float2*)&cov[((size_t)d * CCH + c) * NPX + n], o);
        }
    }
}

// ---------------------------------------------------------------------------
extern "C" void kernel_launch(void* const* d_in, const int* in_sizes, int n_in,
                              void* d_out, int out_size) {
    const float* x = (const float*)d_in[0];
    float* out  = (float*)d_out;
    float* mean = out;                          // [C, N]
    float* cov  = out + (size_t)CCH * NPX;      // [C, C, N]

    static bool attr_set = false;
    const int smem_bytes = NBUF * BUFSZ * 4;    // 131,072 B
    if (!attr_set) {
        cudaFuncSetAttribute(mvg_fused_kernel,
                             cudaFuncAttributeMaxDynamicSharedMemorySize,
                             smem_bytes);
        attr_set = true;
    }
    dim3 grid(36, NPX / TN);                    // (36, 128)
    mvg_fused_kernel<<<grid, 256, smem_bytes>>>(x, mean, cov);
}

// round 17
// speedup vs baseline: 1.1014x; 1.0310x over previous
#include <cuda_runtime.h>
#include <cstdint>

#define BSZ 32
#define CCH 256
#define NPX 4096
#define REGF 0.01f

#define TN  32                      // n per block
#define KB  4                       // b per chunk
#define KBTN (KB * TN)              // row stride in floats (128)
#define NCHUNK (BSZ / KB)           // 8
#define BUFSZ (64 * KBTN)           // 8192 floats (32 KB)
#define NBUF 4                      // 128 KB staging
#define XCHG (NBUF * BUFSZ)         // float offset of sum-exchange region

typedef unsigned long long ull;

// packed fp32x2 FMA (2 FMAs/instr); ptxas never emits from C++.
__device__ __forceinline__ void ffma2(ull& acc, ull a, ull b) {
    asm("fma.rn.f32x2 %0, %1, %2, %0;" : "+l"(acc) : "l"(a), "l"(b));
}
__device__ __forceinline__ unsigned smem_u32(const void* p) {
    return (unsigned)__cvta_generic_to_shared(p);
}
__device__ __forceinline__ void cp16(unsigned s, const float* g) {
    asm volatile("cp.async.cg.shared.global [%0], [%1], 16;" :: "r"(s), "l"(g));
}
#define CP_COMMIT() asm volatile("cp.async.commit_group;" ::: "memory")
#define CP_WAIT2()  asm volatile("cp.async.wait_group 2;" ::: "memory")

#define ONE2 0x3f8000003f800000ull   // packed {1.0f, 1.0f}

// ---------------------------------------------------------------------------
// Fused kernel: mean AND covariance in one pass.
//   cov[c,d,n] = (Sxx - Sx_c*Sx_d/B)/(B-1) + REG*(c==d);  mean = Sx/B.
// Block = 32c x 32d tile pair (36 upper-tri pairs, mirrored) x 32 n.
// Thread microtile 8c x 8d x 2n packed f32x2, with per-thread ROW ROTATION:
//   av[i] <-> row tc*8 + ((i+2*td)&7),  bv[j] <-> row td*8 + ((j+2*tc)&7)
// so each thread sums only av[0..1] and bv[0..1] (4 sum-FFMA2/bb instead of
// 16; every (row,n) sum computed exactly once block-wide). Sums exchanged
// through an 8KB smem region after the mainloop; gathered for the mean
// write and the rank-1 correction. No separate mean kernel, no mean loads.
// Pipeline: cp.async, 4 buffers, 3 chunks in flight, one sync per chunk.
// ---------------------------------------------------------------------------
__global__ __launch_bounds__(256, 1)
void mvg_fused_kernel(const float* __restrict__ x,
                      float* __restrict__ mean,
                      float* __restrict__ cov) {
    // upper-triangular tile pair (ti <= tj) from blockIdx.x in [0,36)
    int rem = blockIdx.x;
    int ti = 0, row8 = 8;
    while (rem >= row8) { rem -= row8; row8--; ti++; }
    const int tj = ti + rem;
    const bool diag = (ti == tj);
    const int n0 = blockIdx.y * TN;

    extern __shared__ float sm[];
    ull* sumA = (ull*)(sm + XCHG);           // [32 rows][16 tn]
    ull* sumB = sumA + 32 * 16;              // [32 rows][16 tn]

    const int tid = threadIdx.x;
    const int tn  = tid & 15;        // n-pair index (2 n per thread)
    const int tcd = tid >> 4;
    const int tc  = tcd & 3;         // 8 c-rows
    const int td  = tcd >> 2;        // 8 d-rows (warp-uniform)

    // r-invariant staging fields: f = r*256 + tid
    const int n4 = tid & 7;          // float4 column (0..7)
    const int sb = (tid >> 3) & 3;   // batch-within-chunk
    const int r0 = tid >> 5;         // base row (0..7); row = r0 + 8r

    const float* gc_base = x + ((size_t)sb * CCH + ti * 32 + r0) * NPX + n0 + n4 * 4;
    const float* gd_base = x + ((size_t)sb * CCH + tj * 32 + r0) * NPX + n0 + n4 * 4;
    const unsigned sm_off = (unsigned)(((r0 * KB + sb) * TN + n4 * 4) * 4);

    // ---- stage chunk ck into buffer ck % NBUF (fully unrolled) ----
    auto stage = [&](int ck) {
        const unsigned dst = smem_u32(sm)
            + (unsigned)((ck & (NBUF - 1)) * BUFSZ * 4) + sm_off;
        const size_t gofs = (size_t)(ck * KB) * CCH * NPX;
        const float* gc = gc_base + gofs;
#pragma unroll
        for (int r = 0; r < 4; r++)   // c-rows r0 + 8r (0..31)
            cp16(dst + (unsigned)(r * 8 * KBTN * 4), gc + (size_t)r * 8 * NPX);
        if (!diag) {
            const float* gd = gd_base + gofs;
            const unsigned ddst = dst + (unsigned)(32 * KBTN * 4);
#pragma unroll
            for (int r = 0; r < 4; r++)  // d-rows
                cp16(ddst + (unsigned)(r * 8 * KBTN * 4), gd + (size_t)r * 8 * NPX);
        }
        CP_COMMIT();
    };

    // rotated row offsets (floats), constant per thread
    int offA[8], offB[8];
#pragma unroll
    for (int i = 0; i < 8; i++) offA[i] = ((i + 2 * td) & 7) * KBTN;
#pragma unroll
    for (int j = 0; j < 8; j++) offB[j] = ((j + 2 * tc) & 7) * KBTN;

    ull acc[8][8];
    ull as0 = 0ull, as1 = 0ull, bs0 = 0ull, bs1 = 0ull;
#pragma unroll
    for (int i = 0; i < 8; i++)
#pragma unroll
        for (int j = 0; j < 8; j++) acc[i][j] = 0ull;

    const int drow0 = diag ? 0 : 32;

    auto compute = [&](int ck) {
        const float* buf = sm + (ck & (NBUF - 1)) * BUFSZ;
        const float* pa = buf + (tc * 8) * KBTN + 2 * tn;
        const float* pb = buf + (drow0 + td * 8) * KBTN + 2 * tn;
#pragma unroll
        for (int bb = 0; bb < KB; bb++) {
            ull av[8], bv[8];
#pragma unroll
            for (int i = 0; i < 8; i++)
                av[i] = *(const ull*)&pa[offA[i] + bb * TN];
#pragma unroll
            for (int j = 0; j < 8; j++)
                bv[j] = *(const ull*)&pb[offB[j] + bb * TN];
            ffma2(as0, av[0], ONE2);
            ffma2(as1, av[1], ONE2);
            ffma2(bs0, bv[0], ONE2);
            ffma2(bs1, bv[1], ONE2);
#pragma unroll
            for (int i = 0; i < 8; i++)
#pragma unroll
                for (int j = 0; j < 8; j++)
                    ffma2(acc[i][j], av[i], bv[j]);
        }
    };

    // ---- pipeline: 4 buffers, 3 chunks in flight, one sync per chunk ----
    stage(0); stage(1); stage(2);
#pragma unroll
    for (int ck = 0; ck < NCHUNK; ck++) {
        CP_WAIT2();                  // groups 0..ck complete
        __syncthreads();             // data visible; prev compute done
        compute(ck);
        if (ck + 3 < NCHUNK) stage(ck + 3);
        else CP_COMMIT();            // empty group keeps wait count aligned
    }

    // ---- exchange row sums (each computed exactly once block-wide) ----
    // av[0..1] are rows tc*8 + 2*td + {0,1}; bv[0..1] are rows td*8 + 2*tc + {0,1}
    sumA[(tc * 8 + 2 * td + 0) * 16 + tn] = as0;
    sumA[(tc * 8 + 2 * td + 1) * 16 + tn] = as1;
    sumB[(td * 8 + 2 * tc + 0) * 16 + tn] = bs0;
    sumB[(td * 8 + 2 * tc + 1) * 16 + tn] = bs1;
    __syncthreads();

    float2 ma[8], mb[8];             // raw sums matching acc's rotated rows
#pragma unroll
    for (int i = 0; i < 8; i++) {
        ull a = sumA[(tc * 8 + ((i + 2 * td) & 7)) * 16 + tn];
        ma[i] = make_float2(__uint_as_float((unsigned)(a & 0xffffffffull)),
                            __uint_as_float((unsigned)(a >> 32)));
    }
#pragma unroll
    for (int j = 0; j < 8; j++) {
        ull b = sumB[(td * 8 + ((j + 2 * tc) & 7)) * 16 + tn];
        mb[j] = make_float2(__uint_as_float((unsigned)(b & 0xffffffffull)),
                            __uint_as_float((unsigned)(b >> 32)));
    }

    const float scale = 1.0f / (BSZ - 1);
    const float invB  = 1.0f / BSZ;
    const int n = n0 + 2 * tn;

    // mean: diagonal blocks, td==0 threads (rotation is identity there)
    if (diag && td == 0) {
#pragma unroll
        for (int i = 0; i < 8; i++) {
            const int c = ti * 32 + tc * 8 + i;
            __stcs((float2*)&mean[(size_t)c * NPX + n],
                   make_float2(ma[i].x * invB, ma[i].y * invB));
        }
    }

#pragma unroll
    for (int i = 0; i < 8; i++) {
        const int c = ti * 32 + tc * 8 + ((i + 2 * td) & 7);
#pragma unroll
        for (int j = 0; j < 8; j++) {
            const int d = tj * 32 + td * 8 + ((j + 2 * tc) & 7);
            ull a = acc[i][j];
            float lo = __uint_as_float((unsigned)(a & 0xffffffffull));
            float hi = __uint_as_float((unsigned)(a >> 32));
            lo = (lo - ma[i].x * mb[j].x * invB) * scale;
            hi = (hi - ma[i].y * mb[j].y * invB) * scale;
            if (c == d) { lo += REGF; hi += REGF; }
            float2 o = make_float2(lo, hi);
            __stcs((float2*)&cov[((size_t)c * CCH + d) * NPX + n], o);
            if (!diag)
                __stcs((float2*)&cov[((size_t)d * CCH + c) * NPX + n], o);
        }
    }
}

// ---------------------------------------------------------------------------
extern "C" void kernel_launch(void* const* d_in, const int* in_sizes, int n_in,
                              void* d_out, int out_size) {
    const float* x = (const float*)d_in[0];
    float* out  = (float*)d_out;
    float* mean = out;                          // [C, N]
    float* cov  = out + (size_t)CCH * NPX;      // [C, C, N]

    static bool attr_set = false;
    const int smem_bytes = (XCHG + 2 * 32 * 16 * 2) * 4;  // 131072 + 8192 B
    if (!attr_set) {
        cudaFuncSetAttribute(mvg_fused_kernel,
                             cudaFuncAttributeMaxDynamicSharedMemorySize,
                             smem_bytes);
        attr_set = true;
    }
    dim3 grid(36, NPX / TN);                    // (36, 128)
    mvg_fused_kernel<<<grid, 256, smem_bytes>>>(x, mean, cov);
}